// round 1
// baseline (speedup 1.0000x reference)
#include <cuda_runtime.h>
#include <math.h>

#define B 2
#define S 2048
#define D 1024
#define H 16
#define DK 64

#define LOG2E 1.4426950408889634f

// ---------------------------------------------------------------------------
// Scratch (no allocations allowed -> __device__ globals)
// ---------------------------------------------------------------------------
__device__ float g_Qp[B * S * D];
__device__ float g_Kp[B * S * D];
__device__ float g_Vp[B * S * D];
__device__ float g_attn[B * S * D];
__device__ float g_cos[S * 32];
__device__ float g_sin[S * 32];

// ---------------------------------------------------------------------------
// RoPE tables: cos/sin(t * base^(-f/32)) computed in fp64 for phase accuracy
// ---------------------------------------------------------------------------
__global__ void rope_table_kernel() {
    int idx = blockIdx.x * blockDim.x + threadIdx.x;
    if (idx >= S * 32) return;
    int s = idx >> 5;
    int f = idx & 31;
    double inv = exp(-((double)f / 32.0) * log(500000.0));
    double ph = (double)s * inv;
    g_cos[idx] = (float)cos(ph);
    g_sin[idx] = (float)sin(ph);
}

// ---------------------------------------------------------------------------
// NT GEMM: Y[m][n] = sum_k X[m][k] * W[n][k]
// 64x64 tile, BK=16, 256 threads, 4x4 micro-tile per thread.
// blockIdx.z selects (X,W,Y) triple so 3 projections run as one launch.
// ---------------------------------------------------------------------------
__global__ __launch_bounds__(256) void gemm_nt_kernel(
    const float* __restrict__ X0, const float* __restrict__ X1, const float* __restrict__ X2,
    const float* __restrict__ W0, const float* __restrict__ W1, const float* __restrict__ W2,
    float* __restrict__ Y0, float* __restrict__ Y1, float* __restrict__ Y2,
    int M, int N, int K)
{
    __shared__ float As[16][68];
    __shared__ float Bs[16][68];

    const float* X;
    const float* W;
    float* Y;
    if (blockIdx.z == 0)      { X = X0; W = W0; Y = Y0; }
    else if (blockIdx.z == 1) { X = X1; W = W1; Y = Y1; }
    else                      { X = X2; W = W2; Y = Y2; }

    int tid = threadIdx.x;
    int tx = tid & 15;
    int ty = tid >> 4;
    int m0 = blockIdx.y * 64;
    int n0 = blockIdx.x * 64;

    int lr = tid >> 2;          // 0..63 : row within tile
    int lc = (tid & 3) * 4;     // 0,4,8,12 : k offset within tile

    const float* xrow = X + (size_t)(m0 + lr) * K + lc;
    const float* wrow = W + (size_t)(n0 + lr) * K + lc;

    float acc[4][4] = {};

    for (int k0 = 0; k0 < K; k0 += 16) {
        float4 a = *(const float4*)(xrow + k0);
        float4 b = *(const float4*)(wrow + k0);
        __syncthreads();
        As[lc + 0][lr] = a.x; As[lc + 1][lr] = a.y; As[lc + 2][lr] = a.z; As[lc + 3][lr] = a.w;
        Bs[lc + 0][lr] = b.x; Bs[lc + 1][lr] = b.y; Bs[lc + 2][lr] = b.z; Bs[lc + 3][lr] = b.w;
        __syncthreads();
#pragma unroll
        for (int kk = 0; kk < 16; kk++) {
            float4 av = *(const float4*)&As[kk][ty * 4];
            float4 bv = *(const float4*)&Bs[kk][tx * 4];
            acc[0][0] += av.x * bv.x; acc[0][1] += av.x * bv.y; acc[0][2] += av.x * bv.z; acc[0][3] += av.x * bv.w;
            acc[1][0] += av.y * bv.x; acc[1][1] += av.y * bv.y; acc[1][2] += av.y * bv.z; acc[1][3] += av.y * bv.w;
            acc[2][0] += av.z * bv.x; acc[2][1] += av.z * bv.y; acc[2][2] += av.z * bv.z; acc[2][3] += av.z * bv.w;
            acc[3][0] += av.w * bv.x; acc[3][1] += av.w * bv.y; acc[3][2] += av.w * bv.z; acc[3][3] += av.w * bv.w;
        }
    }

#pragma unroll
    for (int ii = 0; ii < 4; ii++) {
        float4 r = make_float4(acc[ii][0], acc[ii][1], acc[ii][2], acc[ii][3]);
        *(float4*)(Y + (size_t)(m0 + ty * 4 + ii) * N + n0 + tx * 4) = r;
    }
}

// ---------------------------------------------------------------------------
// Fused per-head RMSNorm + RoPE, in place on Qp / Kp. One warp per (b,s,h).
// ---------------------------------------------------------------------------
__global__ __launch_bounds__(256) void norm_rope_kernel(
    float* __restrict__ Qp, float* __restrict__ Kp,
    const float* __restrict__ qw, const float* __restrict__ kw)
{
    int lane = threadIdx.x & 31;
    int idx = blockIdx.x * 8 + (threadIdx.x >> 5);   // (b*S + s)*H + h
    float* basep = (blockIdx.y == 0) ? Qp : Kp;
    const float* w = (blockIdx.y == 0) ? qw : kw;
    float* ptr = basep + (size_t)idx * 64;
    int s = (idx >> 4) & (S - 1);

    float x0 = ptr[lane];
    float x1 = ptr[lane + 32];
    float ss = x0 * x0 + x1 * x1;
    ss += __shfl_xor_sync(0xffffffffu, ss, 1);
    ss += __shfl_xor_sync(0xffffffffu, ss, 2);
    ss += __shfl_xor_sync(0xffffffffu, ss, 4);
    ss += __shfl_xor_sync(0xffffffffu, ss, 8);
    ss += __shfl_xor_sync(0xffffffffu, ss, 16);
    float inv = rsqrtf(ss * (1.0f / 64.0f) + 1e-10f);

    float n0 = w[lane] * x0 * inv;
    float n1 = w[lane + 32] * x1 * inv;

    float c = g_cos[s * 32 + lane];
    float sn = g_sin[s * 32 + lane];
    // out[d] = x[d]*cos + rot(x)[d]*sin ; rot = [-x2, x1]
    ptr[lane]      = n0 * c - n1 * sn;
    ptr[lane + 32] = n1 * c + n0 * sn;
}

// ---------------------------------------------------------------------------
// Causal flash attention. One CTA = 64 query rows of one (b,h).
// Qs/Ks d-major (transposed), Vs/Ps j-major. 4x4 micro-tiles, online softmax.
// ---------------------------------------------------------------------------
__global__ __launch_bounds__(256) void flash_attn_kernel(
    const float* __restrict__ Qp, const float* __restrict__ Kp,
    const float* __restrict__ Vp, float* __restrict__ Op)
{
    extern __shared__ float sm[];
    float* Qs = sm;               // [64][68] Qs[d][i], pre-scaled by 1/8
    float* Ks = sm + 64 * 68;     // [64][68] Ks[d][j]
    float* Vs = sm + 2 * 64 * 68; // [64][68] Vs[j][d]
    float* Ps = sm + 3 * 64 * 68; // [64][68] Ps[j][i]

    int tid = threadIdx.x;
    int tx = tid & 15;
    int ty = tid >> 4;
    int qt = blockIdx.x;
    int bh = blockIdx.y;
    int b = bh >> 4;
    int h = bh & 15;
    int q0 = qt * 64;

    size_t base = (size_t)b * S * D + (size_t)h * DK;

    int li = tid >> 2;            // 0..63
    int ld0 = (tid & 3) * 16;     // 0,16,32,48

    // Load Q tile transposed, folding in softmax scale 1/sqrt(64)
    {
        const float* qrow = Qp + base + (size_t)(q0 + li) * D + ld0;
#pragma unroll
        for (int u = 0; u < 4; u++) {
            float4 v = *(const float4*)(qrow + u * 4);
            int d = ld0 + u * 4;
            Qs[(d + 0) * 68 + li] = v.x * 0.125f;
            Qs[(d + 1) * 68 + li] = v.y * 0.125f;
            Qs[(d + 2) * 68 + li] = v.z * 0.125f;
            Qs[(d + 3) * 68 + li] = v.w * 0.125f;
        }
    }

    float o[4][4] = {};
    float m[4], l[4];
#pragma unroll
    for (int i = 0; i < 4; i++) { m[i] = -1e30f; l[i] = 0.0f; }

    for (int kt = 0; kt <= qt; kt++) {
        int k0 = kt * 64;
        __syncthreads();   // previous iteration done reading Ks/Vs/Ps
        {
            const float* krow = Kp + base + (size_t)(k0 + li) * D + ld0;
            const float* vrow = Vp + base + (size_t)(k0 + li) * D + ld0;
#pragma unroll
            for (int u = 0; u < 4; u++) {
                int d = ld0 + u * 4;
                float4 kv = *(const float4*)(krow + u * 4);
                Ks[(d + 0) * 68 + li] = kv.x;
                Ks[(d + 1) * 68 + li] = kv.y;
                Ks[(d + 2) * 68 + li] = kv.z;
                Ks[(d + 3) * 68 + li] = kv.w;
                float4 vv = *(const float4*)(vrow + u * 4);
                *(float4*)&Vs[li * 68 + d] = vv;
            }
        }
        __syncthreads();

        // S = Q K^T (scale already folded into Q)
        float sc[4][4] = {};
#pragma unroll 16
        for (int d = 0; d < 64; d++) {
            float4 qv = *(const float4*)&Qs[d * 68 + ty * 4];
            float4 kv = *(const float4*)&Ks[d * 68 + tx * 4];
            sc[0][0] += qv.x * kv.x; sc[0][1] += qv.x * kv.y; sc[0][2] += qv.x * kv.z; sc[0][3] += qv.x * kv.w;
            sc[1][0] += qv.y * kv.x; sc[1][1] += qv.y * kv.y; sc[1][2] += qv.y * kv.z; sc[1][3] += qv.y * kv.w;
            sc[2][0] += qv.z * kv.x; sc[2][1] += qv.z * kv.y; sc[2][2] += qv.z * kv.z; sc[2][3] += qv.z * kv.w;
            sc[3][0] += qv.w * kv.x; sc[3][1] += qv.w * kv.y; sc[3][2] += qv.w * kv.z; sc[3][3] += qv.w * kv.w;
        }

        if (kt == qt) {
#pragma unroll
            for (int ii = 0; ii < 4; ii++)
#pragma unroll
                for (int jj = 0; jj < 4; jj++)
                    if (tx * 4 + jj > ty * 4 + ii) sc[ii][jj] = -1e30f;
        }

        // online softmax update (rows of a 4-row group live on 16 lanes of one half-warp)
#pragma unroll
        for (int ii = 0; ii < 4; ii++) {
            float rm = fmaxf(fmaxf(sc[ii][0], sc[ii][1]), fmaxf(sc[ii][2], sc[ii][3]));
            rm = fmaxf(rm, __shfl_xor_sync(0xffffffffu, rm, 1));
            rm = fmaxf(rm, __shfl_xor_sync(0xffffffffu, rm, 2));
            rm = fmaxf(rm, __shfl_xor_sync(0xffffffffu, rm, 4));
            rm = fmaxf(rm, __shfl_xor_sync(0xffffffffu, rm, 8));
            float mn = fmaxf(m[ii], rm);
            float al = exp2f((m[ii] - mn) * LOG2E);
            m[ii] = mn;

            float rs = 0.0f;
#pragma unroll
            for (int jj = 0; jj < 4; jj++) {
                sc[ii][jj] = exp2f((sc[ii][jj] - mn) * LOG2E);
                rs += sc[ii][jj];
            }
            rs += __shfl_xor_sync(0xffffffffu, rs, 1);
            rs += __shfl_xor_sync(0xffffffffu, rs, 2);
            rs += __shfl_xor_sync(0xffffffffu, rs, 4);
            rs += __shfl_xor_sync(0xffffffffu, rs, 8);
            l[ii] = l[ii] * al + rs;

            o[ii][0] *= al; o[ii][1] *= al; o[ii][2] *= al; o[ii][3] *= al;
        }

        // write P transposed: Ps[j][i]
#pragma unroll
        for (int jj = 0; jj < 4; jj++) {
            float4 pv = make_float4(sc[0][jj], sc[1][jj], sc[2][jj], sc[3][jj]);
            *(float4*)&Ps[(tx * 4 + jj) * 68 + ty * 4] = pv;
        }
        __syncthreads();

        // O += P V
#pragma unroll 16
        for (int j = 0; j < 64; j++) {
            float4 pv = *(const float4*)&Ps[j * 68 + ty * 4];
            float4 vv = *(const float4*)&Vs[j * 68 + tx * 4];
            o[0][0] += pv.x * vv.x; o[0][1] += pv.x * vv.y; o[0][2] += pv.x * vv.z; o[0][3] += pv.x * vv.w;
            o[1][0] += pv.y * vv.x; o[1][1] += pv.y * vv.y; o[1][2] += pv.y * vv.z; o[1][3] += pv.y * vv.w;
            o[2][0] += pv.z * vv.x; o[2][1] += pv.z * vv.y; o[2][2] += pv.z * vv.z; o[2][3] += pv.z * vv.w;
            o[3][0] += pv.w * vv.x; o[3][1] += pv.w * vv.y; o[3][2] += pv.w * vv.z; o[3][3] += pv.w * vv.w;
        }
    }

#pragma unroll
    for (int ii = 0; ii < 4; ii++) {
        float invl = 1.0f / l[ii];
        float4 r = make_float4(o[ii][0] * invl, o[ii][1] * invl, o[ii][2] * invl, o[ii][3] * invl);
        *(float4*)(Op + base + (size_t)(q0 + ty * 4 + ii) * D + tx * 4) = r;
    }
}

// ---------------------------------------------------------------------------
// Launch
// ---------------------------------------------------------------------------
extern "C" void kernel_launch(void* const* d_in, const int* in_sizes, int n_in,
                              void* d_out, int out_size)
{
    const float* q  = (const float*)d_in[0];
    const float* k  = (const float*)d_in[1];
    const float* v  = (const float*)d_in[2];
    const float* Wq = (const float*)d_in[3];
    const float* Wk = (const float*)d_in[4];
    const float* Wv = (const float*)d_in[5];
    const float* Wo = (const float*)d_in[6];
    const float* qw = (const float*)d_in[7];
    const float* kw = (const float*)d_in[8];
    float* out = (float*)d_out;

    float *Qp, *Kp, *Vp, *At;
    cudaGetSymbolAddress((void**)&Qp, g_Qp);
    cudaGetSymbolAddress((void**)&Kp, g_Kp);
    cudaGetSymbolAddress((void**)&Vp, g_Vp);
    cudaGetSymbolAddress((void**)&At, g_attn);

    // 1) RoPE tables
    rope_table_kernel<<<(S * 32 + 255) / 256, 256>>>();

    // 2) Q/K/V projections (x @ W^T), batched over grid.z
    dim3 gproj(D / 64, (B * S) / 64, 3);
    gemm_nt_kernel<<<gproj, 256>>>(q, k, v, Wq, Wk, Wv, Qp, Kp, Vp, B * S, D, D);

    // 3) per-head RMSNorm + RoPE in place on Q, K
    norm_rope_kernel<<<dim3((B * S * H) / 8, 2), 256>>>(Qp, Kp, qw, kw);

    // 4) causal flash attention -> g_attn (heads merged)
    int smem_bytes = 4 * 64 * 68 * sizeof(float);
    cudaFuncSetAttribute(flash_attn_kernel, cudaFuncAttributeMaxDynamicSharedMemorySize, smem_bytes);
    flash_attn_kernel<<<dim3(S / 64, B * H), 256, smem_bytes>>>(Qp, Kp, Vp, At);

    // 5) output projection attn @ Wo^T -> d_out
    dim3 gout(D / 64, (B * S) / 64, 1);
    gemm_nt_kernel<<<gout, 256>>>(At, At, At, Wo, Wo, Wo, out, out, out, B * S, D, D);
}

// round 4
// speedup vs baseline: 1.5311x; 1.5311x over previous
#include <cuda_runtime.h>
#include <cuda_bf16.h>
#include <math.h>
#include <stdint.h>

#define B 2
#define S 2048
#define D 1024
#define H 16
#define DK 64
#define GK 1024
#define GN 1024

#define LOG2E 1.4426950408889634f

// ---------------------------------------------------------------------------
// Scratch (no allocations allowed -> __device__ globals)
// ---------------------------------------------------------------------------
__device__ float g_Qp[B * S * D];
__device__ float g_Kp[B * S * D];
__device__ float g_Vp[B * S * D];
__device__ float g_attn[B * S * D];
__device__ float g_cos[S * 32];
__device__ float g_sin[S * 32];

// ---------------------------------------------------------------------------
// RoPE tables
// ---------------------------------------------------------------------------
__global__ void rope_table_kernel() {
    int idx = blockIdx.x * blockDim.x + threadIdx.x;
    if (idx >= S * 32) return;
    int s = idx >> 5;
    int f = idx & 31;
    double inv = exp(-((double)f / 32.0) * log(500000.0));
    double ph = (double)s * inv;
    g_cos[idx] = (float)cos(ph);
    g_sin[idx] = (float)sin(ph);
}

// ---------------------------------------------------------------------------
// mma.sync helper: D(f32) += A(bf16) * B(bf16), m16n8k16
// ---------------------------------------------------------------------------
__device__ __forceinline__ void mma16816(float* c, const uint32_t* a, const uint32_t* b) {
    asm volatile(
        "mma.sync.aligned.m16n8k16.row.col.f32.bf16.bf16.f32 "
        "{%0,%1,%2,%3}, {%4,%5,%6,%7}, {%8,%9}, {%0,%1,%2,%3};"
        : "+f"(c[0]), "+f"(c[1]), "+f"(c[2]), "+f"(c[3])
        : "r"(a[0]), "r"(a[1]), "r"(a[2]), "r"(a[3]), "r"(b[0]), "r"(b[1]));
}

// SMEM tile layout: [128 rows][32 bf16 cols] = 64B per row, XOR-swizzled 16B chunks
__device__ __forceinline__ uint32_t swz(int row, int bytecol) {
    return (uint32_t)(row * 64 + ((((bytecol >> 4) ^ (row & 3)) << 4) | (bytecol & 15)));
}

// ---------------------------------------------------------------------------
// bf16x3 tensor-core NT GEMM: Y[m][n] = sum_k X[m][k] * W[n][k]
// CTA: 128x128, 8 warps (2x4), warp tile 64x32, BK=32, double-buffered smem.
// ---------------------------------------------------------------------------
#define TILE_B 8192           // one 128x32 bf16 tile
#define STAGE_B (4 * TILE_B)  // AHI, ALO, BHI, BLO
#define GEMM_SMEM (2 * STAGE_B)

__global__ __launch_bounds__(256) void gemm_mma_kernel(
    const float* __restrict__ X0, const float* __restrict__ X1, const float* __restrict__ X2,
    const float* __restrict__ W0, const float* __restrict__ W1, const float* __restrict__ W2,
    float* __restrict__ Y0, float* __restrict__ Y1, float* __restrict__ Y2)
{
    extern __shared__ char smc[];

    const float* X; const float* W; float* Y;
    if (blockIdx.z == 0)      { X = X0; W = W0; Y = Y0; }
    else if (blockIdx.z == 1) { X = X1; W = W1; Y = Y1; }
    else                      { X = X2; W = W2; Y = Y2; }

    int tid = threadIdx.x;
    int warp = tid >> 5;
    int lane = tid & 31;
    int wm0 = (warp >> 2) * 64;   // warp m offset in tile
    int wn0 = (warp & 3) * 32;    // warp n offset
    int m0 = blockIdx.y * 128;
    int n0 = blockIdx.x * 128;

    // gmem staging: thread covers rows lr+32i, float cols lc..lc+3 of the chunk
    int lr = tid >> 3;
    int lc = (tid & 7) * 4;

    const float* Xb = X + (size_t)m0 * GK;
    const float* Wb = W + (size_t)n0 * GK;

    float acc[4][4][4];
#pragma unroll
    for (int i = 0; i < 4; i++)
#pragma unroll
        for (int j = 0; j < 4; j++)
#pragma unroll
            for (int q = 0; q < 4; q++) acc[i][j][q] = 0.0f;

    float4 xv[4], wv[4];

    // prologue: load + convert + store chunk 0 into stage 0
#pragma unroll
    for (int i = 0; i < 4; i++) {
        xv[i] = *(const float4*)(Xb + (size_t)(lr + 32 * i) * GK + lc);
        wv[i] = *(const float4*)(Wb + (size_t)(lr + 32 * i) * GK + lc);
    }
    {
        char* st = smc;
#pragma unroll
        for (int i = 0; i < 4; i++) {
            int row = lr + 32 * i;
            uint32_t sa = swz(row, lc * 2);
            __nv_bfloat162 h0 = __floats2bfloat162_rn(xv[i].x, xv[i].y);
            __nv_bfloat162 h1 = __floats2bfloat162_rn(xv[i].z, xv[i].w);
            __nv_bfloat162 l0 = __floats2bfloat162_rn(xv[i].x - __bfloat162float(h0.x),
                                                      xv[i].y - __bfloat162float(h0.y));
            __nv_bfloat162 l1 = __floats2bfloat162_rn(xv[i].z - __bfloat162float(h1.x),
                                                      xv[i].w - __bfloat162float(h1.y));
            uint2 uh, ul;
            uh.x = *(uint32_t*)&h0; uh.y = *(uint32_t*)&h1;
            ul.x = *(uint32_t*)&l0; ul.y = *(uint32_t*)&l1;
            *(uint2*)(st + 0 * TILE_B + sa) = uh;
            *(uint2*)(st + 1 * TILE_B + sa) = ul;
            __nv_bfloat162 g0 = __floats2bfloat162_rn(wv[i].x, wv[i].y);
            __nv_bfloat162 g1 = __floats2bfloat162_rn(wv[i].z, wv[i].w);
            __nv_bfloat162 m0v = __floats2bfloat162_rn(wv[i].x - __bfloat162float(g0.x),
                                                       wv[i].y - __bfloat162float(g0.y));
            __nv_bfloat162 m1v = __floats2bfloat162_rn(wv[i].z - __bfloat162float(g1.x),
                                                       wv[i].w - __bfloat162float(g1.y));
            uint2 vh, vl;
            vh.x = *(uint32_t*)&g0; vh.y = *(uint32_t*)&g1;
            vl.x = *(uint32_t*)&m0v; vl.y = *(uint32_t*)&m1v;
            *(uint2*)(st + 2 * TILE_B + sa) = vh;
            *(uint2*)(st + 3 * TILE_B + sa) = vl;
        }
    }
    __syncthreads();

    for (int kc = 0; kc < GK / 32; kc++) {
        int cs = kc & 1;
        char* rd = smc + cs * STAGE_B;

        bool more = (kc + 1 < GK / 32);
        if (more) {
            const float* Xp = Xb + (kc + 1) * 32;
            const float* Wp = Wb + (kc + 1) * 32;
#pragma unroll
            for (int i = 0; i < 4; i++) {
                xv[i] = *(const float4*)(Xp + (size_t)(lr + 32 * i) * GK + lc);
                wv[i] = *(const float4*)(Wp + (size_t)(lr + 32 * i) * GK + lc);
            }
        }

        // compute from stage cs
#pragma unroll
        for (int ks = 0; ks < 2; ks++) {
            int bcol0 = ks * 32 + (lane & 3) * 4;   // byte col of k-pair
            // B fragments (hi & lo), 4 n-frags
            uint32_t bh[4][2], bl[4][2];
            int brow = wn0 + (lane >> 2);
#pragma unroll
            for (int ni = 0; ni < 4; ni++) {
                uint32_t s0 = swz(brow + ni * 8, bcol0);
                uint32_t s1 = swz(brow + ni * 8, bcol0 + 16);
                bh[ni][0] = *(const uint32_t*)(rd + 2 * TILE_B + s0);
                bh[ni][1] = *(const uint32_t*)(rd + 2 * TILE_B + s1);
                bl[ni][0] = *(const uint32_t*)(rd + 3 * TILE_B + s0);
                bl[ni][1] = *(const uint32_t*)(rd + 3 * TILE_B + s1);
            }
#pragma unroll
            for (int mi = 0; mi < 4; mi++) {
                int arow = wm0 + mi * 16 + (lane >> 2);
                uint32_t s00 = swz(arow, bcol0);
                uint32_t s10 = swz(arow + 8, bcol0);
                uint32_t s01 = swz(arow, bcol0 + 16);
                uint32_t s11 = swz(arow + 8, bcol0 + 16);
                uint32_t ah[4], al[4];
                ah[0] = *(const uint32_t*)(rd + 0 * TILE_B + s00);
                ah[1] = *(const uint32_t*)(rd + 0 * TILE_B + s10);
                ah[2] = *(const uint32_t*)(rd + 0 * TILE_B + s01);
                ah[3] = *(const uint32_t*)(rd + 0 * TILE_B + s11);
                al[0] = *(const uint32_t*)(rd + 1 * TILE_B + s00);
                al[1] = *(const uint32_t*)(rd + 1 * TILE_B + s10);
                al[2] = *(const uint32_t*)(rd + 1 * TILE_B + s01);
                al[3] = *(const uint32_t*)(rd + 1 * TILE_B + s11);
#pragma unroll
                for (int ni = 0; ni < 4; ni++) {
                    mma16816(acc[mi][ni], ah, bh[ni]);
                    mma16816(acc[mi][ni], ah, bl[ni]);
                    mma16816(acc[mi][ni], al, bh[ni]);
                }
            }
        }

        if (more) {
            char* st = smc + (cs ^ 1) * STAGE_B;
#pragma unroll
            for (int i = 0; i < 4; i++) {
                int row = lr + 32 * i;
                uint32_t sa = swz(row, lc * 2);
                __nv_bfloat162 h0 = __floats2bfloat162_rn(xv[i].x, xv[i].y);
                __nv_bfloat162 h1 = __floats2bfloat162_rn(xv[i].z, xv[i].w);
                __nv_bfloat162 l0 = __floats2bfloat162_rn(xv[i].x - __bfloat162float(h0.x),
                                                          xv[i].y - __bfloat162float(h0.y));
                __nv_bfloat162 l1 = __floats2bfloat162_rn(xv[i].z - __bfloat162float(h1.x),
                                                          xv[i].w - __bfloat162float(h1.y));
                uint2 uh, ul;
                uh.x = *(uint32_t*)&h0; uh.y = *(uint32_t*)&h1;
                ul.x = *(uint32_t*)&l0; ul.y = *(uint32_t*)&l1;
                *(uint2*)(st + 0 * TILE_B + sa) = uh;
                *(uint2*)(st + 1 * TILE_B + sa) = ul;
                __nv_bfloat162 g0 = __floats2bfloat162_rn(wv[i].x, wv[i].y);
                __nv_bfloat162 g1 = __floats2bfloat162_rn(wv[i].z, wv[i].w);
                __nv_bfloat162 m0v = __floats2bfloat162_rn(wv[i].x - __bfloat162float(g0.x),
                                                           wv[i].y - __bfloat162float(g0.y));
                __nv_bfloat162 m1v = __floats2bfloat162_rn(wv[i].z - __bfloat162float(g1.x),
                                                           wv[i].w - __bfloat162float(g1.y));
                uint2 vh, vl;
                vh.x = *(uint32_t*)&g0; vh.y = *(uint32_t*)&g1;
                vl.x = *(uint32_t*)&m0v; vl.y = *(uint32_t*)&m1v;
                *(uint2*)(st + 2 * TILE_B + sa) = vh;
                *(uint2*)(st + 3 * TILE_B + sa) = vl;
            }
            __syncthreads();
        }
    }

    // epilogue
#pragma unroll
    for (int mi = 0; mi < 4; mi++) {
        int r = m0 + wm0 + mi * 16 + (lane >> 2);
#pragma unroll
        for (int ni = 0; ni < 4; ni++) {
            int cl = n0 + wn0 + ni * 8 + (lane & 3) * 2;
            float2 v0 = make_float2(acc[mi][ni][0], acc[mi][ni][1]);
            float2 v1 = make_float2(acc[mi][ni][2], acc[mi][ni][3]);
            *(float2*)(Y + (size_t)r * GN + cl) = v0;
            *(float2*)(Y + (size_t)(r + 8) * GN + cl) = v1;
        }
    }
}

// ---------------------------------------------------------------------------
// Fused per-head RMSNorm + RoPE, in place on Qp / Kp. One warp per (b,s,h).
// ---------------------------------------------------------------------------
__global__ __launch_bounds__(256) void norm_rope_kernel(
    float* __restrict__ Qp, float* __restrict__ Kp,
    const float* __restrict__ qw, const float* __restrict__ kw)
{
    int lane = threadIdx.x & 31;
    int idx = blockIdx.x * 8 + (threadIdx.x >> 5);   // (b*S + s)*H + h
    float* basep = (blockIdx.y == 0) ? Qp : Kp;
    const float* w = (blockIdx.y == 0) ? qw : kw;
    float* ptr = basep + (size_t)idx * 64;
    int s = (idx >> 4) & (S - 1);

    float x0 = ptr[lane];
    float x1 = ptr[lane + 32];
    float ss = x0 * x0 + x1 * x1;
    ss += __shfl_xor_sync(0xffffffffu, ss, 1);
    ss += __shfl_xor_sync(0xffffffffu, ss, 2);
    ss += __shfl_xor_sync(0xffffffffu, ss, 4);
    ss += __shfl_xor_sync(0xffffffffu, ss, 8);
    ss += __shfl_xor_sync(0xffffffffu, ss, 16);
    float inv = rsqrtf(ss * (1.0f / 64.0f) + 1e-10f);

    float n0 = w[lane] * x0 * inv;
    float n1 = w[lane + 32] * x1 * inv;

    float c = g_cos[s * 32 + lane];
    float sn = g_sin[s * 32 + lane];
    ptr[lane]      = n0 * c - n1 * sn;
    ptr[lane + 32] = n1 * c + n0 * sn;
}

// ---------------------------------------------------------------------------
// Causal flash attention (fp32). One CTA = 64 query rows of one (b,h).
// ---------------------------------------------------------------------------
__global__ __launch_bounds__(256) void flash_attn_kernel(
    const float* __restrict__ Qp, const float* __restrict__ Kp,
    const float* __restrict__ Vp, float* __restrict__ Op)
{
    extern __shared__ float sm[];
    float* Qs = sm;               // [64][68] Qs[d][i], pre-scaled by 1/8
    float* Ks = sm + 64 * 68;     // [64][68] Ks[d][j]
    float* Vs = sm + 2 * 64 * 68; // [64][68] Vs[j][d]
    float* Ps = sm + 3 * 64 * 68; // [64][68] Ps[j][i]

    int tid = threadIdx.x;
    int tx = tid & 15;
    int ty = tid >> 4;
    int qt = blockIdx.x;
    int bh = blockIdx.y;
    int b = bh >> 4;
    int h = bh & 15;
    int q0 = qt * 64;

    size_t base = (size_t)b * S * D + (size_t)h * DK;

    int li = tid >> 2;
    int ld0 = (tid & 3) * 16;

    {
        const float* qrow = Qp + base + (size_t)(q0 + li) * D + ld0;
#pragma unroll
        for (int u = 0; u < 4; u++) {
            float4 v = *(const float4*)(qrow + u * 4);
            int d = ld0 + u * 4;
            Qs[(d + 0) * 68 + li] = v.x * 0.125f;
            Qs[(d + 1) * 68 + li] = v.y * 0.125f;
            Qs[(d + 2) * 68 + li] = v.z * 0.125f;
            Qs[(d + 3) * 68 + li] = v.w * 0.125f;
        }
    }

    float o[4][4] = {};
    float m[4], l[4];
#pragma unroll
    for (int i = 0; i < 4; i++) { m[i] = -1e30f; l[i] = 0.0f; }

    for (int kt = 0; kt <= qt; kt++) {
        int k0 = kt * 64;
        __syncthreads();
        {
            const float* krow = Kp + base + (size_t)(k0 + li) * D + ld0;
            const float* vrow = Vp + base + (size_t)(k0 + li) * D + ld0;
#pragma unroll
            for (int u = 0; u < 4; u++) {
                int d = ld0 + u * 4;
                float4 kv = *(const float4*)(krow + u * 4);
                Ks[(d + 0) * 68 + li] = kv.x;
                Ks[(d + 1) * 68 + li] = kv.y;
                Ks[(d + 2) * 68 + li] = kv.z;
                Ks[(d + 3) * 68 + li] = kv.w;
                float4 vv = *(const float4*)(vrow + u * 4);
                *(float4*)&Vs[li * 68 + d] = vv;
            }
        }
        __syncthreads();

        float sc[4][4] = {};
#pragma unroll 16
        for (int d = 0; d < 64; d++) {
            float4 qv = *(const float4*)&Qs[d * 68 + ty * 4];
            float4 kv = *(const float4*)&Ks[d * 68 + tx * 4];
            sc[0][0] += qv.x * kv.x; sc[0][1] += qv.x * kv.y; sc[0][2] += qv.x * kv.z; sc[0][3] += qv.x * kv.w;
            sc[1][0] += qv.y * kv.x; sc[1][1] += qv.y * kv.y; sc[1][2] += qv.y * kv.z; sc[1][3] += qv.y * kv.w;
            sc[2][0] += qv.z * kv.x; sc[2][1] += qv.z * kv.y; sc[2][2] += qv.z * kv.z; sc[2][3] += qv.z * kv.w;
            sc[3][0] += qv.w * kv.x; sc[3][1] += qv.w * kv.y; sc[3][2] += qv.w * kv.z; sc[3][3] += qv.w * kv.w;
        }

        if (kt == qt) {
#pragma unroll
            for (int ii = 0; ii < 4; ii++)
#pragma unroll
                for (int jj = 0; jj < 4; jj++)
                    if (tx * 4 + jj > ty * 4 + ii) sc[ii][jj] = -1e30f;
        }

#pragma unroll
        for (int ii = 0; ii < 4; ii++) {
            float rm = fmaxf(fmaxf(sc[ii][0], sc[ii][1]), fmaxf(sc[ii][2], sc[ii][3]));
            rm = fmaxf(rm, __shfl_xor_sync(0xffffffffu, rm, 1));
            rm = fmaxf(rm, __shfl_xor_sync(0xffffffffu, rm, 2));
            rm = fmaxf(rm, __shfl_xor_sync(0xffffffffu, rm, 4));
            rm = fmaxf(rm, __shfl_xor_sync(0xffffffffu, rm, 8));
            float mn = fmaxf(m[ii], rm);
            float al = exp2f((m[ii] - mn) * LOG2E);
            m[ii] = mn;

            float rs = 0.0f;
#pragma unroll
            for (int jj = 0; jj < 4; jj++) {
                sc[ii][jj] = exp2f((sc[ii][jj] - mn) * LOG2E);
                rs += sc[ii][jj];
            }
            rs += __shfl_xor_sync(0xffffffffu, rs, 1);
            rs += __shfl_xor_sync(0xffffffffu, rs, 2);
            rs += __shfl_xor_sync(0xffffffffu, rs, 4);
            rs += __shfl_xor_sync(0xffffffffu, rs, 8);
            l[ii] = l[ii] * al + rs;

            o[ii][0] *= al; o[ii][1] *= al; o[ii][2] *= al; o[ii][3] *= al;
        }

#pragma unroll
        for (int jj = 0; jj < 4; jj++) {
            float4 pv = make_float4(sc[0][jj], sc[1][jj], sc[2][jj], sc[3][jj]);
            *(float4*)&Ps[(tx * 4 + jj) * 68 + ty * 4] = pv;
        }
        __syncthreads();

#pragma unroll 16
        for (int j = 0; j < 64; j++) {
            float4 pv = *(const float4*)&Ps[j * 68 + ty * 4];
            float4 vv = *(const float4*)&Vs[j * 68 + tx * 4];
            o[0][0] += pv.x * vv.x; o[0][1] += pv.x * vv.y; o[0][2] += pv.x * vv.z; o[0][3] += pv.x * vv.w;
            o[1][0] += pv.y * vv.x; o[1][1] += pv.y * vv.y; o[1][2] += pv.y * vv.z; o[1][3] += pv.y * vv.w;
            o[2][0] += pv.z * vv.x; o[2][1] += pv.z * vv.y; o[2][2] += pv.z * vv.z; o[2][3] += pv.z * vv.w;
            o[3][0] += pv.w * vv.x; o[3][1] += pv.w * vv.y; o[3][2] += pv.w * vv.z; o[3][3] += pv.w * vv.w;
        }
    }

#pragma unroll
    for (int ii = 0; ii < 4; ii++) {
        float invl = 1.0f / l[ii];
        float4 r = make_float4(o[ii][0] * invl, o[ii][1] * invl, o[ii][2] * invl, o[ii][3] * invl);
        *(float4*)(Op + base + (size_t)(q0 + ty * 4 + ii) * D + tx * 4) = r;
    }
}

// ---------------------------------------------------------------------------
// Launch
// ---------------------------------------------------------------------------
extern "C" void kernel_launch(void* const* d_in, const int* in_sizes, int n_in,
                              void* d_out, int out_size)
{
    const float* q  = (const float*)d_in[0];
    const float* k  = (const float*)d_in[1];
    const float* v  = (const float*)d_in[2];
    const float* Wq = (const float*)d_in[3];
    const float* Wk = (const float*)d_in[4];
    const float* Wv = (const float*)d_in[5];
    const float* Wo = (const float*)d_in[6];
    const float* qw = (const float*)d_in[7];
    const float* kw = (const float*)d_in[8];
    float* out = (float*)d_out;

    float *Qp, *Kp, *Vp, *At;
    cudaGetSymbolAddress((void**)&Qp, g_Qp);
    cudaGetSymbolAddress((void**)&Kp, g_Kp);
    cudaGetSymbolAddress((void**)&Vp, g_Vp);
    cudaGetSymbolAddress((void**)&At, g_attn);

    // 1) RoPE tables
    rope_table_kernel<<<(S * 32 + 255) / 256, 256>>>();

    // 2) Q/K/V projections via bf16x3 mma.sync GEMM (batched over grid.z)
    cudaFuncSetAttribute(gemm_mma_kernel, cudaFuncAttributeMaxDynamicSharedMemorySize, GEMM_SMEM);
    dim3 gproj(GN / 128, (B * S) / 128, 3);
    gemm_mma_kernel<<<gproj, 256, GEMM_SMEM>>>(q, k, v, Wq, Wk, Wv, Qp, Kp, Vp);

    // 3) per-head RMSNorm + RoPE in place on Q, K
    norm_rope_kernel<<<dim3((B * S * H) / 8, 2), 256>>>(Qp, Kp, qw, kw);

    // 4) causal flash attention -> g_attn (heads merged)
    int smem_bytes = 4 * 64 * 68 * sizeof(float);
    cudaFuncSetAttribute(flash_attn_kernel, cudaFuncAttributeMaxDynamicSharedMemorySize, smem_bytes);
    flash_attn_kernel<<<dim3(S / 64, B * H), 256, smem_bytes>>>(Qp, Kp, Vp, At);

    // 5) output projection attn @ Wo^T -> d_out
    dim3 gout(GN / 128, (B * S) / 128, 1);
    gemm_mma_kernel<<<gout, 256, GEMM_SMEM>>>(At, At, At, Wo, Wo, Wo, out, out, out);
}

// round 5
// speedup vs baseline: 2.5027x; 1.6346x over previous
#include <cuda_runtime.h>
#include <cuda_bf16.h>
#include <math.h>
#include <stdint.h>

#define B 2
#define S 2048
#define D 1024
#define H 16
#define DK 64
#define GK 1024
#define GN 1024

#define LOG2E 1.4426950408889634f

// ---------------------------------------------------------------------------
// Scratch (no allocations allowed -> __device__ globals)
// ---------------------------------------------------------------------------
__device__ float g_Qp[B * S * D];
__device__ float g_Kp[B * S * D];
__device__ float g_Vp[B * S * D];
__device__ float g_attn[B * S * D];
__device__ float g_cos[S * 32];
__device__ float g_sin[S * 32];
__device__ __nv_bfloat16 g_Qhi[B * S * D];
__device__ __nv_bfloat16 g_Qlo[B * S * D];
__device__ __nv_bfloat16 g_Khi[B * S * D];
__device__ __nv_bfloat16 g_Klo[B * S * D];
__device__ __nv_bfloat16 g_Vthi[B * H * DK * S];
__device__ __nv_bfloat16 g_Vtlo[B * H * DK * S];

// ---------------------------------------------------------------------------
// RoPE tables
// ---------------------------------------------------------------------------
__global__ void rope_table_kernel() {
    int idx = blockIdx.x * blockDim.x + threadIdx.x;
    if (idx >= S * 32) return;
    int s = idx >> 5;
    int f = idx & 31;
    double inv = exp(-((double)f / 32.0) * log(500000.0));
    double ph = (double)s * inv;
    g_cos[idx] = (float)cos(ph);
    g_sin[idx] = (float)sin(ph);
}

// ---------------------------------------------------------------------------
// mma.sync helper: D(f32) += A(bf16) * B(bf16), m16n8k16
// ---------------------------------------------------------------------------
__device__ __forceinline__ void mma16816(float* c, const uint32_t* a, const uint32_t* b) {
    asm volatile(
        "mma.sync.aligned.m16n8k16.row.col.f32.bf16.bf16.f32 "
        "{%0,%1,%2,%3}, {%4,%5,%6,%7}, {%8,%9}, {%0,%1,%2,%3};"
        : "+f"(c[0]), "+f"(c[1]), "+f"(c[2]), "+f"(c[3])
        : "r"(a[0]), "r"(a[1]), "r"(a[2]), "r"(a[3]), "r"(b[0]), "r"(b[1]));
}

__device__ __forceinline__ void pack_hilo(float x0, float x1, uint32_t& hi, uint32_t& lo) {
    __nv_bfloat162 h = __floats2bfloat162_rn(x0, x1);
    float r0 = x0 - __bfloat162float(h.x);
    float r1 = x1 - __bfloat162float(h.y);
    __nv_bfloat162 l = __floats2bfloat162_rn(r0, r1);
    hi = *(uint32_t*)&h;
    lo = *(uint32_t*)&l;
}

// SMEM tile layout (GEMM): [128 rows][32 bf16 cols] = 64B rows, XOR 16B swizzle
__device__ __forceinline__ uint32_t swz(int row, int bytecol) {
    return (uint32_t)(row * 64 + ((((bytecol >> 4) ^ (row & 3)) << 4) | (bytecol & 15)));
}

// ---------------------------------------------------------------------------
// bf16x3 tensor-core NT GEMM (unchanged from R4 pass)
// ---------------------------------------------------------------------------
#define TILE_B 8192
#define STAGE_B (4 * TILE_B)
#define GEMM_SMEM (2 * STAGE_B)

__global__ __launch_bounds__(256) void gemm_mma_kernel(
    const float* __restrict__ X0, const float* __restrict__ X1, const float* __restrict__ X2,
    const float* __restrict__ W0, const float* __restrict__ W1, const float* __restrict__ W2,
    float* __restrict__ Y0, float* __restrict__ Y1, float* __restrict__ Y2)
{
    extern __shared__ char smc[];

    const float* X; const float* W; float* Y;
    if (blockIdx.z == 0)      { X = X0; W = W0; Y = Y0; }
    else if (blockIdx.z == 1) { X = X1; W = W1; Y = Y1; }
    else                      { X = X2; W = W2; Y = Y2; }

    int tid = threadIdx.x;
    int warp = tid >> 5;
    int lane = tid & 31;
    int wm0 = (warp >> 2) * 64;
    int wn0 = (warp & 3) * 32;
    int m0 = blockIdx.y * 128;
    int n0 = blockIdx.x * 128;

    int lr = tid >> 3;
    int lc = (tid & 7) * 4;

    const float* Xb = X + (size_t)m0 * GK;
    const float* Wb = W + (size_t)n0 * GK;

    float acc[4][4][4];
#pragma unroll
    for (int i = 0; i < 4; i++)
#pragma unroll
        for (int j = 0; j < 4; j++)
#pragma unroll
            for (int q = 0; q < 4; q++) acc[i][j][q] = 0.0f;

    float4 xv[4], wv[4];

#pragma unroll
    for (int i = 0; i < 4; i++) {
        xv[i] = *(const float4*)(Xb + (size_t)(lr + 32 * i) * GK + lc);
        wv[i] = *(const float4*)(Wb + (size_t)(lr + 32 * i) * GK + lc);
    }
    {
        char* st = smc;
#pragma unroll
        for (int i = 0; i < 4; i++) {
            int row = lr + 32 * i;
            uint32_t sa = swz(row, lc * 2);
            uint2 uh, ul, vh, vl;
            pack_hilo(xv[i].x, xv[i].y, uh.x, ul.x);
            pack_hilo(xv[i].z, xv[i].w, uh.y, ul.y);
            pack_hilo(wv[i].x, wv[i].y, vh.x, vl.x);
            pack_hilo(wv[i].z, wv[i].w, vh.y, vl.y);
            *(uint2*)(st + 0 * TILE_B + sa) = uh;
            *(uint2*)(st + 1 * TILE_B + sa) = ul;
            *(uint2*)(st + 2 * TILE_B + sa) = vh;
            *(uint2*)(st + 3 * TILE_B + sa) = vl;
        }
    }
    __syncthreads();

    for (int kc = 0; kc < GK / 32; kc++) {
        int cs = kc & 1;
        char* rd = smc + cs * STAGE_B;

        bool more = (kc + 1 < GK / 32);
        if (more) {
            const float* Xp = Xb + (kc + 1) * 32;
            const float* Wp = Wb + (kc + 1) * 32;
#pragma unroll
            for (int i = 0; i < 4; i++) {
                xv[i] = *(const float4*)(Xp + (size_t)(lr + 32 * i) * GK + lc);
                wv[i] = *(const float4*)(Wp + (size_t)(lr + 32 * i) * GK + lc);
            }
        }

#pragma unroll
        for (int ks = 0; ks < 2; ks++) {
            int bcol0 = ks * 32 + (lane & 3) * 4;
            uint32_t bh[4][2], bl[4][2];
            int brow = wn0 + (lane >> 2);
#pragma unroll
            for (int ni = 0; ni < 4; ni++) {
                uint32_t s0 = swz(brow + ni * 8, bcol0);
                uint32_t s1 = swz(brow + ni * 8, bcol0 + 16);
                bh[ni][0] = *(const uint32_t*)(rd + 2 * TILE_B + s0);
                bh[ni][1] = *(const uint32_t*)(rd + 2 * TILE_B + s1);
                bl[ni][0] = *(const uint32_t*)(rd + 3 * TILE_B + s0);
                bl[ni][1] = *(const uint32_t*)(rd + 3 * TILE_B + s1);
            }
#pragma unroll
            for (int mi = 0; mi < 4; mi++) {
                int arow = wm0 + mi * 16 + (lane >> 2);
                uint32_t s00 = swz(arow, bcol0);
                uint32_t s10 = swz(arow + 8, bcol0);
                uint32_t s01 = swz(arow, bcol0 + 16);
                uint32_t s11 = swz(arow + 8, bcol0 + 16);
                uint32_t ah[4], al[4];
                ah[0] = *(const uint32_t*)(rd + 0 * TILE_B + s00);
                ah[1] = *(const uint32_t*)(rd + 0 * TILE_B + s10);
                ah[2] = *(const uint32_t*)(rd + 0 * TILE_B + s01);
                ah[3] = *(const uint32_t*)(rd + 0 * TILE_B + s11);
                al[0] = *(const uint32_t*)(rd + 1 * TILE_B + s00);
                al[1] = *(const uint32_t*)(rd + 1 * TILE_B + s10);
                al[2] = *(const uint32_t*)(rd + 1 * TILE_B + s01);
                al[3] = *(const uint32_t*)(rd + 1 * TILE_B + s11);
#pragma unroll
                for (int ni = 0; ni < 4; ni++) {
                    mma16816(acc[mi][ni], ah, bh[ni]);
                    mma16816(acc[mi][ni], ah, bl[ni]);
                    mma16816(acc[mi][ni], al, bh[ni]);
                }
            }
        }

        if (more) {
            char* st = smc + (cs ^ 1) * STAGE_B;
#pragma unroll
            for (int i = 0; i < 4; i++) {
                int row = lr + 32 * i;
                uint32_t sa = swz(row, lc * 2);
                uint2 uh, ul, vh, vl;
                pack_hilo(xv[i].x, xv[i].y, uh.x, ul.x);
                pack_hilo(xv[i].z, xv[i].w, uh.y, ul.y);
                pack_hilo(wv[i].x, wv[i].y, vh.x, vl.x);
                pack_hilo(wv[i].z, wv[i].w, vh.y, vl.y);
                *(uint2*)(st + 0 * TILE_B + sa) = uh;
                *(uint2*)(st + 1 * TILE_B + sa) = ul;
                *(uint2*)(st + 2 * TILE_B + sa) = vh;
                *(uint2*)(st + 3 * TILE_B + sa) = vl;
            }
            __syncthreads();
        }
    }

#pragma unroll
    for (int mi = 0; mi < 4; mi++) {
        int r = m0 + wm0 + mi * 16 + (lane >> 2);
#pragma unroll
        for (int ni = 0; ni < 4; ni++) {
            int cl = n0 + wn0 + ni * 8 + (lane & 3) * 2;
            *(float2*)(Y + (size_t)r * GN + cl) = make_float2(acc[mi][ni][0], acc[mi][ni][1]);
            *(float2*)(Y + (size_t)(r + 8) * GN + cl) = make_float2(acc[mi][ni][2], acc[mi][ni][3]);
        }
    }
}

// ---------------------------------------------------------------------------
// Fused per-head RMSNorm + RoPE -> bf16 hi/lo tensors. Q gets 1/8 folded in.
// ---------------------------------------------------------------------------
__global__ __launch_bounds__(256) void norm_rope_kernel(
    const float* __restrict__ Qp, const float* __restrict__ Kp,
    const float* __restrict__ qw, const float* __restrict__ kw)
{
    int lane = threadIdx.x & 31;
    int idx = blockIdx.x * 8 + (threadIdx.x >> 5);   // (b*S + s)*H + h
    int isQ = (blockIdx.y == 0);
    const float* basep = isQ ? Qp : Kp;
    const float* w = isQ ? qw : kw;
    __nv_bfloat16* outhi = isQ ? g_Qhi : g_Khi;
    __nv_bfloat16* outlo = isQ ? g_Qlo : g_Klo;
    const float* ptr = basep + (size_t)idx * 64;
    int s = (idx >> 4) & (S - 1);

    float x0 = ptr[lane];
    float x1 = ptr[lane + 32];
    float ss = x0 * x0 + x1 * x1;
    ss += __shfl_xor_sync(0xffffffffu, ss, 1);
    ss += __shfl_xor_sync(0xffffffffu, ss, 2);
    ss += __shfl_xor_sync(0xffffffffu, ss, 4);
    ss += __shfl_xor_sync(0xffffffffu, ss, 8);
    ss += __shfl_xor_sync(0xffffffffu, ss, 16);
    float inv = rsqrtf(ss * (1.0f / 64.0f) + 1e-10f);

    float n0 = w[lane] * x0 * inv;
    float n1 = w[lane + 32] * x1 * inv;

    float c = g_cos[s * 32 + lane];
    float sn = g_sin[s * 32 + lane];
    float y0 = n0 * c - n1 * sn;
    float y1 = n1 * c + n0 * sn;
    if (isQ) { y0 *= 0.125f; y1 *= 0.125f; }

    __nv_bfloat16 h0 = __float2bfloat16_rn(y0);
    __nv_bfloat16 h1 = __float2bfloat16_rn(y1);
    __nv_bfloat16 l0 = __float2bfloat16_rn(y0 - __bfloat162float(h0));
    __nv_bfloat16 l1 = __float2bfloat16_rn(y1 - __bfloat162float(h1));
    outhi[(size_t)idx * 64 + lane] = h0;
    outhi[(size_t)idx * 64 + lane + 32] = h1;
    outlo[(size_t)idx * 64 + lane] = l0;
    outlo[(size_t)idx * 64 + lane + 32] = l1;
}

// ---------------------------------------------------------------------------
// V split + transpose:  g_Vt{hi,lo}[bh][dk][s] = split(V[b][s][h*64+dk])
// ---------------------------------------------------------------------------
__global__ __launch_bounds__(256) void v_transpose_kernel(const float* __restrict__ Vp) {
    __shared__ float t[64][65];
    int tid = threadIdx.x;
    int bh = blockIdx.y;
    int b = bh >> 4;
    int h = bh & 15;
    int s0 = blockIdx.x * 64;

#pragma unroll
    for (int it = 0; it < 16; it++) {
        int e = tid + it * 256;
        int i = e >> 6;
        int dk = e & 63;
        t[i][dk] = Vp[(size_t)(b * S + s0 + i) * D + h * 64 + dk];
    }
    __syncthreads();
#pragma unroll
    for (int it = 0; it < 16; it++) {
        int e = tid + it * 256;
        int dk = e >> 6;
        int j = e & 63;
        float v = t[j][dk];
        __nv_bfloat16 hi = __float2bfloat16_rn(v);
        __nv_bfloat16 lo = __float2bfloat16_rn(v - __bfloat162float(hi));
        size_t o = (size_t)(bh * 64 + dk) * S + s0 + j;
        g_Vthi[o] = hi;
        g_Vtlo[o] = lo;
    }
}

// ---------------------------------------------------------------------------
// Tensor-core causal flash attention (bf16x3). CTA = 128 q rows of one (b,h).
// 8 warps x 16 rows. K-tiles of 64. K/Vt staged in swizzled SMEM.
// ---------------------------------------------------------------------------
// 128B-row swizzle for 64x64 bf16 tiles
#define FSA(row, bc) ((uint32_t)((row) * 128 + ((bc) ^ (((row) & 7) << 4))))

__global__ __launch_bounds__(256) void flash_mma_kernel(float* __restrict__ Op) {
    __shared__ char sm[32768];
    // main loop tiles: KHI@0, KLO@8192, VHI@16384, VLO@24576 (each 64x128B)
    // Q staging (before loop): QHI@0 (16KB), QLO@16384 (16KB)

    int tid = threadIdx.x;
    int w = tid >> 5;
    int lane = tid & 31;
    int qt = (int)gridDim.x - 1 - (int)blockIdx.x;   // heavy tiles first
    int bh = blockIdx.y;
    int b = bh >> 4;
    int h = bh & 15;
    int q0 = qt * 128;
    int r0 = lane >> 2;
    int qd = (lane & 3);
    int qrow = q0 + w * 16;

    size_t qkbase = (size_t)b * S * D + h * 64;
    size_t vtbase = (size_t)bh * 64 * S;

    // ---- stage Q, build fragments ----
#pragma unroll
    for (int it = 0; it < 4; it++) {
        int ch = tid + it * 256;       // 0..1023
        int row = ch >> 3;
        int cc = ch & 7;
        uint32_t sa = FSA(row, cc * 16);
        *(uint4*)(sm + sa) = *((const uint4*)(g_Qhi + qkbase + (size_t)(q0 + row) * D) + cc);
        *(uint4*)(sm + 16384 + sa) = *((const uint4*)(g_Qlo + qkbase + (size_t)(q0 + row) * D) + cc);
    }
    __syncthreads();

    uint32_t qh[4][4], ql[4][4];
    {
        int rA = w * 16 + r0;
#pragma unroll
        for (int kk = 0; kk < 4; kk++) {
            int bc = kk * 32 + qd * 4;
            uint32_t s00 = FSA(rA, bc);
            uint32_t s10 = FSA(rA + 8, bc);
            uint32_t s01 = FSA(rA, bc + 16);
            uint32_t s11 = FSA(rA + 8, bc + 16);
            qh[kk][0] = *(const uint32_t*)(sm + s00);
            qh[kk][1] = *(const uint32_t*)(sm + s10);
            qh[kk][2] = *(const uint32_t*)(sm + s01);
            qh[kk][3] = *(const uint32_t*)(sm + s11);
            ql[kk][0] = *(const uint32_t*)(sm + 16384 + s00);
            ql[kk][1] = *(const uint32_t*)(sm + 16384 + s10);
            ql[kk][2] = *(const uint32_t*)(sm + 16384 + s01);
            ql[kk][3] = *(const uint32_t*)(sm + 16384 + s11);
        }
    }

    float o[8][4];
#pragma unroll
    for (int n = 0; n < 8; n++)
#pragma unroll
        for (int j = 0; j < 4; j++) o[n][j] = 0.0f;
    float m0 = -1e30f, m1 = -1e30f, l0 = 0.0f, l1 = 0.0f;

    int ktmax = 2 * qt + 1;
    for (int kt = 0; kt <= ktmax; kt++) {
        int k0 = kt * 64;
        __syncthreads();
        // stage K (hi/lo) and Vt (hi/lo)
#pragma unroll
        for (int it = 0; it < 2; it++) {
            int ch = tid + it * 256;    // 0..511
            int row = ch >> 3;
            int cc = ch & 7;
            uint32_t sa = FSA(row, cc * 16);
            *(uint4*)(sm + sa)         = *((const uint4*)(g_Khi + qkbase + (size_t)(k0 + row) * D) + cc);
            *(uint4*)(sm + 8192 + sa)  = *((const uint4*)(g_Klo + qkbase + (size_t)(k0 + row) * D) + cc);
            *(uint4*)(sm + 16384 + sa) = *((const uint4*)(g_Vthi + vtbase + (size_t)row * S + k0) + cc);
            *(uint4*)(sm + 24576 + sa) = *((const uint4*)(g_Vtlo + vtbase + (size_t)row * S + k0) + cc);
        }
        __syncthreads();

        if (k0 <= qrow + 15) {
            // ---- S = Q K^T ----
            float s[8][4];
#pragma unroll
            for (int n = 0; n < 8; n++)
#pragma unroll
                for (int j = 0; j < 4; j++) s[n][j] = 0.0f;
#pragma unroll
            for (int n = 0; n < 8; n++) {
                int br = n * 8 + r0;
#pragma unroll
                for (int kk = 0; kk < 4; kk++) {
                    int bc = kk * 32 + qd * 4;
                    uint32_t sa0 = FSA(br, bc);
                    uint32_t sa1 = FSA(br, bc + 16);
                    uint32_t bhf[2], blf[2];
                    bhf[0] = *(const uint32_t*)(sm + sa0);
                    bhf[1] = *(const uint32_t*)(sm + sa1);
                    blf[0] = *(const uint32_t*)(sm + 8192 + sa0);
                    blf[1] = *(const uint32_t*)(sm + 8192 + sa1);
                    mma16816(s[n], qh[kk], bhf);
                    mma16816(s[n], qh[kk], blf);
                    mma16816(s[n], ql[kk], bhf);
                }
            }

            // causal mask on diagonal-straddling tiles
            if (k0 + 63 > qrow) {
                int rq0 = qrow + r0;
#pragma unroll
                for (int n = 0; n < 8; n++) {
                    int c0 = k0 + n * 8 + qd * 2;
                    if (c0 > rq0) s[n][0] = -1e30f;
                    if (c0 + 1 > rq0) s[n][1] = -1e30f;
                    if (c0 > rq0 + 8) s[n][2] = -1e30f;
                    if (c0 + 1 > rq0 + 8) s[n][3] = -1e30f;
                }
            }

            // ---- online softmax ----
            float rm0 = -1e30f, rm1 = -1e30f;
#pragma unroll
            for (int n = 0; n < 8; n++) {
                rm0 = fmaxf(rm0, fmaxf(s[n][0], s[n][1]));
                rm1 = fmaxf(rm1, fmaxf(s[n][2], s[n][3]));
            }
            rm0 = fmaxf(rm0, __shfl_xor_sync(0xffffffffu, rm0, 1));
            rm0 = fmaxf(rm0, __shfl_xor_sync(0xffffffffu, rm0, 2));
            rm1 = fmaxf(rm1, __shfl_xor_sync(0xffffffffu, rm1, 1));
            rm1 = fmaxf(rm1, __shfl_xor_sync(0xffffffffu, rm1, 2));
            float mn0 = fmaxf(m0, rm0);
            float mn1 = fmaxf(m1, rm1);
            float al0 = exp2f((m0 - mn0) * LOG2E);
            float al1 = exp2f((m1 - mn1) * LOG2E);
            m0 = mn0; m1 = mn1;

            float rs0 = 0.0f, rs1 = 0.0f;
#pragma unroll
            for (int n = 0; n < 8; n++) {
                s[n][0] = exp2f((s[n][0] - mn0) * LOG2E);
                s[n][1] = exp2f((s[n][1] - mn0) * LOG2E);
                s[n][2] = exp2f((s[n][2] - mn1) * LOG2E);
                s[n][3] = exp2f((s[n][3] - mn1) * LOG2E);
                rs0 += s[n][0] + s[n][1];
                rs1 += s[n][2] + s[n][3];
            }
            rs0 += __shfl_xor_sync(0xffffffffu, rs0, 1);
            rs0 += __shfl_xor_sync(0xffffffffu, rs0, 2);
            rs1 += __shfl_xor_sync(0xffffffffu, rs1, 1);
            rs1 += __shfl_xor_sync(0xffffffffu, rs1, 2);
            l0 = l0 * al0 + rs0;
            l1 = l1 * al1 + rs1;
#pragma unroll
            for (int n = 0; n < 8; n++) {
                o[n][0] *= al0; o[n][1] *= al0;
                o[n][2] *= al1; o[n][3] *= al1;
            }

            // ---- P -> A fragments (hi/lo) ----
            uint32_t pah[4][4], pal[4][4];
#pragma unroll
            for (int kk = 0; kk < 4; kk++) {
                pack_hilo(s[2 * kk][0], s[2 * kk][1], pah[kk][0], pal[kk][0]);
                pack_hilo(s[2 * kk][2], s[2 * kk][3], pah[kk][1], pal[kk][1]);
                pack_hilo(s[2 * kk + 1][0], s[2 * kk + 1][1], pah[kk][2], pal[kk][2]);
                pack_hilo(s[2 * kk + 1][2], s[2 * kk + 1][3], pah[kk][3], pal[kk][3]);
            }

            // ---- O += P V ----
#pragma unroll
            for (int n = 0; n < 8; n++) {
                int vr = n * 8 + r0;
#pragma unroll
                for (int kk = 0; kk < 4; kk++) {
                    int bc = kk * 32 + qd * 4;
                    uint32_t sa0 = FSA(vr, bc);
                    uint32_t sa1 = FSA(vr, bc + 16);
                    uint32_t vhf[2], vlf[2];
                    vhf[0] = *(const uint32_t*)(sm + 16384 + sa0);
                    vhf[1] = *(const uint32_t*)(sm + 16384 + sa1);
                    vlf[0] = *(const uint32_t*)(sm + 24576 + sa0);
                    vlf[1] = *(const uint32_t*)(sm + 24576 + sa1);
                    mma16816(o[n], pah[kk], vhf);
                    mma16816(o[n], pah[kk], vlf);
                    mma16816(o[n], pal[kk], vhf);
                }
            }
        }
    }

    // ---- epilogue ----
    float il0 = 1.0f / l0;
    float il1 = 1.0f / l1;
    int rg = q0 + w * 16 + r0;
#pragma unroll
    for (int n = 0; n < 8; n++) {
        int dk = n * 8 + qd * 2;
        *(float2*)(Op + qkbase + (size_t)rg * D + dk) = make_float2(o[n][0] * il0, o[n][1] * il0);
        *(float2*)(Op + qkbase + (size_t)(rg + 8) * D + dk) = make_float2(o[n][2] * il1, o[n][3] * il1);
    }
}

// ---------------------------------------------------------------------------
// Launch
// ---------------------------------------------------------------------------
extern "C" void kernel_launch(void* const* d_in, const int* in_sizes, int n_in,
                              void* d_out, int out_size)
{
    const float* q  = (const float*)d_in[0];
    const float* k  = (const float*)d_in[1];
    const float* v  = (const float*)d_in[2];
    const float* Wq = (const float*)d_in[3];
    const float* Wk = (const float*)d_in[4];
    const float* Wv = (const float*)d_in[5];
    const float* Wo = (const float*)d_in[6];
    const float* qw = (const float*)d_in[7];
    const float* kw = (const float*)d_in[8];
    float* out = (float*)d_out;

    float *Qp, *Kp, *Vp, *At;
    cudaGetSymbolAddress((void**)&Qp, g_Qp);
    cudaGetSymbolAddress((void**)&Kp, g_Kp);
    cudaGetSymbolAddress((void**)&Vp, g_Vp);
    cudaGetSymbolAddress((void**)&At, g_attn);

    // 1) RoPE tables
    rope_table_kernel<<<(S * 32 + 255) / 256, 256>>>();

    // 2) Q/K/V projections via bf16x3 mma.sync GEMM
    cudaFuncSetAttribute(gemm_mma_kernel, cudaFuncAttributeMaxDynamicSharedMemorySize, GEMM_SMEM);
    dim3 gproj(GN / 128, (B * S) / 128, 3);
    gemm_mma_kernel<<<gproj, 256, GEMM_SMEM>>>(q, k, v, Wq, Wk, Wv, Qp, Kp, Vp);

    // 3) per-head RMSNorm + RoPE -> bf16 hi/lo (Q scaled by 1/8)
    norm_rope_kernel<<<dim3((B * S * H) / 8, 2), 256>>>(Qp, Kp, qw, kw);

    // 3b) V -> transposed bf16 hi/lo
    v_transpose_kernel<<<dim3(S / 64, B * H), 256>>>(Vp);

    // 4) tensor-core causal flash attention -> g_attn
    flash_mma_kernel<<<dim3(S / 128, B * H), 256>>>(At);

    // 5) output projection attn @ Wo^T -> d_out
    dim3 gout(GN / 128, (B * S) / 128, 1);
    gemm_mma_kernel<<<gout, 256, GEMM_SMEM>>>(At, At, At, Wo, Wo, Wo, out, out, out);
}

// round 6
// speedup vs baseline: 2.6580x; 1.0620x over previous
#include <cuda_runtime.h>
#include <cuda_bf16.h>
#include <math.h>
#include <stdint.h>

#define B 2
#define S 2048
#define D 1024
#define H 16
#define DK 64
#define GK 1024
#define GN 1024

#define LOG2E 1.4426950408889634f

// ---------------------------------------------------------------------------
// Scratch (no allocations allowed -> __device__ globals)
// ---------------------------------------------------------------------------
__device__ float g_Qp[B * S * D];
__device__ float g_Kp[B * S * D];
__device__ float g_Vp[B * S * D];
__device__ float g_attn[B * S * D];
__device__ float g_cos[S * 32];
__device__ float g_sin[S * 32];
__device__ __nv_bfloat16 g_Qhi[B * S * D];
__device__ __nv_bfloat16 g_Qlo[B * S * D];
__device__ __nv_bfloat16 g_Khi[B * S * D];
__device__ __nv_bfloat16 g_Klo[B * S * D];
__device__ __nv_bfloat16 g_Vthi[B * H * DK * S];
__device__ __nv_bfloat16 g_Vtlo[B * H * DK * S];

// ---------------------------------------------------------------------------
// RoPE tables
// ---------------------------------------------------------------------------
__global__ void rope_table_kernel() {
    int idx = blockIdx.x * blockDim.x + threadIdx.x;
    if (idx >= S * 32) return;
    int s = idx >> 5;
    int f = idx & 31;
    double inv = exp(-((double)f / 32.0) * log(500000.0));
    double ph = (double)s * inv;
    g_cos[idx] = (float)cos(ph);
    g_sin[idx] = (float)sin(ph);
}

// ---------------------------------------------------------------------------
// helpers
// ---------------------------------------------------------------------------
__device__ __forceinline__ uint32_t smem_u32(const void* p) {
    uint32_t a;
    asm("{ .reg .u64 t; cvta.to.shared.u64 t, %1; cvt.u32.u64 %0, t; }" : "=r"(a) : "l"(p));
    return a;
}

#define CP_ASYNC16(dst, src) \
    asm volatile("cp.async.ca.shared.global [%0], [%1], 16;" :: "r"(dst), "l"(src))
#define CP_COMMIT() asm volatile("cp.async.commit_group;" ::: "memory")
#define CP_WAIT(n)  asm volatile("cp.async.wait_group %0;" :: "n"(n) : "memory")

__device__ __forceinline__ void mma16816(float* c, const uint32_t* a, const uint32_t* b) {
    asm volatile(
        "mma.sync.aligned.m16n8k16.row.col.f32.bf16.bf16.f32 "
        "{%0,%1,%2,%3}, {%4,%5,%6,%7}, {%8,%9}, {%0,%1,%2,%3};"
        : "+f"(c[0]), "+f"(c[1]), "+f"(c[2]), "+f"(c[3])
        : "r"(a[0]), "r"(a[1]), "r"(a[2]), "r"(a[3]), "r"(b[0]), "r"(b[1]));
}

__device__ __forceinline__ void pack_hilo(float x0, float x1, uint32_t& hi, uint32_t& lo) {
    __nv_bfloat162 h = __floats2bfloat162_rn(x0, x1);
    float r0 = x0 - __bfloat162float(h.x);
    float r1 = x1 - __bfloat162float(h.y);
    __nv_bfloat162 l = __floats2bfloat162_rn(r0, r1);
    hi = *(uint32_t*)&h;
    lo = *(uint32_t*)&l;
}

// SMEM tile layout (GEMM): [128 rows][32 bf16 cols] = 64B rows, XOR 16B swizzle
__device__ __forceinline__ uint32_t swz(int row, int bytecol) {
    return (uint32_t)(row * 64 + ((((bytecol >> 4) ^ (row & 3)) << 4) | (bytecol & 15)));
}

// ---------------------------------------------------------------------------
// bf16x3 tensor-core NT GEMM (unchanged from R4/R5 pass)
// ---------------------------------------------------------------------------
#define TILE_B 8192
#define STAGE_B (4 * TILE_B)
#define GEMM_SMEM (2 * STAGE_B)

__global__ __launch_bounds__(256) void gemm_mma_kernel(
    const float* __restrict__ X0, const float* __restrict__ X1, const float* __restrict__ X2,
    const float* __restrict__ W0, const float* __restrict__ W1, const float* __restrict__ W2,
    float* __restrict__ Y0, float* __restrict__ Y1, float* __restrict__ Y2)
{
    extern __shared__ char smc[];

    const float* X; const float* W; float* Y;
    if (blockIdx.z == 0)      { X = X0; W = W0; Y = Y0; }
    else if (blockIdx.z == 1) { X = X1; W = W1; Y = Y1; }
    else                      { X = X2; W = W2; Y = Y2; }

    int tid = threadIdx.x;
    int warp = tid >> 5;
    int lane = tid & 31;
    int wm0 = (warp >> 2) * 64;
    int wn0 = (warp & 3) * 32;
    int m0 = blockIdx.y * 128;
    int n0 = blockIdx.x * 128;

    int lr = tid >> 3;
    int lc = (tid & 7) * 4;

    const float* Xb = X + (size_t)m0 * GK;
    const float* Wb = W + (size_t)n0 * GK;

    float acc[4][4][4];
#pragma unroll
    for (int i = 0; i < 4; i++)
#pragma unroll
        for (int j = 0; j < 4; j++)
#pragma unroll
            for (int q = 0; q < 4; q++) acc[i][j][q] = 0.0f;

    float4 xv[4], wv[4];

#pragma unroll
    for (int i = 0; i < 4; i++) {
        xv[i] = *(const float4*)(Xb + (size_t)(lr + 32 * i) * GK + lc);
        wv[i] = *(const float4*)(Wb + (size_t)(lr + 32 * i) * GK + lc);
    }
    {
        char* st = smc;
#pragma unroll
        for (int i = 0; i < 4; i++) {
            int row = lr + 32 * i;
            uint32_t sa = swz(row, lc * 2);
            uint2 uh, ul, vh, vl;
            pack_hilo(xv[i].x, xv[i].y, uh.x, ul.x);
            pack_hilo(xv[i].z, xv[i].w, uh.y, ul.y);
            pack_hilo(wv[i].x, wv[i].y, vh.x, vl.x);
            pack_hilo(wv[i].z, wv[i].w, vh.y, vl.y);
            *(uint2*)(st + 0 * TILE_B + sa) = uh;
            *(uint2*)(st + 1 * TILE_B + sa) = ul;
            *(uint2*)(st + 2 * TILE_B + sa) = vh;
            *(uint2*)(st + 3 * TILE_B + sa) = vl;
        }
    }
    __syncthreads();

    for (int kc = 0; kc < GK / 32; kc++) {
        int cs = kc & 1;
        char* rd = smc + cs * STAGE_B;

        bool more = (kc + 1 < GK / 32);
        if (more) {
            const float* Xp = Xb + (kc + 1) * 32;
            const float* Wp = Wb + (kc + 1) * 32;
#pragma unroll
            for (int i = 0; i < 4; i++) {
                xv[i] = *(const float4*)(Xp + (size_t)(lr + 32 * i) * GK + lc);
                wv[i] = *(const float4*)(Wp + (size_t)(lr + 32 * i) * GK + lc);
            }
        }

#pragma unroll
        for (int ks = 0; ks < 2; ks++) {
            int bcol0 = ks * 32 + (lane & 3) * 4;
            uint32_t bh[4][2], bl[4][2];
            int brow = wn0 + (lane >> 2);
#pragma unroll
            for (int ni = 0; ni < 4; ni++) {
                uint32_t s0 = swz(brow + ni * 8, bcol0);
                uint32_t s1 = swz(brow + ni * 8, bcol0 + 16);
                bh[ni][0] = *(const uint32_t*)(rd + 2 * TILE_B + s0);
                bh[ni][1] = *(const uint32_t*)(rd + 2 * TILE_B + s1);
                bl[ni][0] = *(const uint32_t*)(rd + 3 * TILE_B + s0);
                bl[ni][1] = *(const uint32_t*)(rd + 3 * TILE_B + s1);
            }
#pragma unroll
            for (int mi = 0; mi < 4; mi++) {
                int arow = wm0 + mi * 16 + (lane >> 2);
                uint32_t s00 = swz(arow, bcol0);
                uint32_t s10 = swz(arow + 8, bcol0);
                uint32_t s01 = swz(arow, bcol0 + 16);
                uint32_t s11 = swz(arow + 8, bcol0 + 16);
                uint32_t ah[4], al[4];
                ah[0] = *(const uint32_t*)(rd + 0 * TILE_B + s00);
                ah[1] = *(const uint32_t*)(rd + 0 * TILE_B + s10);
                ah[2] = *(const uint32_t*)(rd + 0 * TILE_B + s01);
                ah[3] = *(const uint32_t*)(rd + 0 * TILE_B + s11);
                al[0] = *(const uint32_t*)(rd + 1 * TILE_B + s00);
                al[1] = *(const uint32_t*)(rd + 1 * TILE_B + s10);
                al[2] = *(const uint32_t*)(rd + 1 * TILE_B + s01);
                al[3] = *(const uint32_t*)(rd + 1 * TILE_B + s11);
#pragma unroll
                for (int ni = 0; ni < 4; ni++) {
                    mma16816(acc[mi][ni], ah, bh[ni]);
                    mma16816(acc[mi][ni], ah, bl[ni]);
                    mma16816(acc[mi][ni], al, bh[ni]);
                }
            }
        }

        if (more) {
            char* st = smc + (cs ^ 1) * STAGE_B;
#pragma unroll
            for (int i = 0; i < 4; i++) {
                int row = lr + 32 * i;
                uint32_t sa = swz(row, lc * 2);
                uint2 uh, ul, vh, vl;
                pack_hilo(xv[i].x, xv[i].y, uh.x, ul.x);
                pack_hilo(xv[i].z, xv[i].w, uh.y, ul.y);
                pack_hilo(wv[i].x, wv[i].y, vh.x, vl.x);
                pack_hilo(wv[i].z, wv[i].w, vh.y, vl.y);
                *(uint2*)(st + 0 * TILE_B + sa) = uh;
                *(uint2*)(st + 1 * TILE_B + sa) = ul;
                *(uint2*)(st + 2 * TILE_B + sa) = vh;
                *(uint2*)(st + 3 * TILE_B + sa) = vl;
            }
            __syncthreads();
        }
    }

#pragma unroll
    for (int mi = 0; mi < 4; mi++) {
        int r = m0 + wm0 + mi * 16 + (lane >> 2);
#pragma unroll
        for (int ni = 0; ni < 4; ni++) {
            int cl = n0 + wn0 + ni * 8 + (lane & 3) * 2;
            *(float2*)(Y + (size_t)r * GN + cl) = make_float2(acc[mi][ni][0], acc[mi][ni][1]);
            *(float2*)(Y + (size_t)(r + 8) * GN + cl) = make_float2(acc[mi][ni][2], acc[mi][ni][3]);
        }
    }
}

// ---------------------------------------------------------------------------
// Fused per-head RMSNorm + RoPE -> bf16 hi/lo tensors. Q gets 1/8 folded in.
// ---------------------------------------------------------------------------
__global__ __launch_bounds__(256) void norm_rope_kernel(
    const float* __restrict__ Qp, const float* __restrict__ Kp,
    const float* __restrict__ qw, const float* __restrict__ kw)
{
    int lane = threadIdx.x & 31;
    int idx = blockIdx.x * 8 + (threadIdx.x >> 5);   // (b*S + s)*H + h
    int isQ = (blockIdx.y == 0);
    const float* basep = isQ ? Qp : Kp;
    const float* w = isQ ? qw : kw;
    __nv_bfloat16* outhi = isQ ? g_Qhi : g_Khi;
    __nv_bfloat16* outlo = isQ ? g_Qlo : g_Klo;
    const float* ptr = basep + (size_t)idx * 64;
    int s = (idx >> 4) & (S - 1);

    float x0 = ptr[lane];
    float x1 = ptr[lane + 32];
    float ss = x0 * x0 + x1 * x1;
    ss += __shfl_xor_sync(0xffffffffu, ss, 1);
    ss += __shfl_xor_sync(0xffffffffu, ss, 2);
    ss += __shfl_xor_sync(0xffffffffu, ss, 4);
    ss += __shfl_xor_sync(0xffffffffu, ss, 8);
    ss += __shfl_xor_sync(0xffffffffu, ss, 16);
    float inv = rsqrtf(ss * (1.0f / 64.0f) + 1e-10f);

    float n0 = w[lane] * x0 * inv;
    float n1 = w[lane + 32] * x1 * inv;

    float c = g_cos[s * 32 + lane];
    float sn = g_sin[s * 32 + lane];
    float y0 = n0 * c - n1 * sn;
    float y1 = n1 * c + n0 * sn;
    if (isQ) { y0 *= 0.125f; y1 *= 0.125f; }

    __nv_bfloat16 h0 = __float2bfloat16_rn(y0);
    __nv_bfloat16 h1 = __float2bfloat16_rn(y1);
    __nv_bfloat16 l0 = __float2bfloat16_rn(y0 - __bfloat162float(h0));
    __nv_bfloat16 l1 = __float2bfloat16_rn(y1 - __bfloat162float(h1));
    outhi[(size_t)idx * 64 + lane] = h0;
    outhi[(size_t)idx * 64 + lane + 32] = h1;
    outlo[(size_t)idx * 64 + lane] = l0;
    outlo[(size_t)idx * 64 + lane + 32] = l1;
}

// ---------------------------------------------------------------------------
// V split + transpose:  g_Vt{hi,lo}[bh][dk][s] = split(V[b][s][h*64+dk])
// ---------------------------------------------------------------------------
__global__ __launch_bounds__(256) void v_transpose_kernel(const float* __restrict__ Vp) {
    __shared__ float t[64][65];
    int tid = threadIdx.x;
    int bh = blockIdx.y;
    int b = bh >> 4;
    int h = bh & 15;
    int s0 = blockIdx.x * 64;

#pragma unroll
    for (int it = 0; it < 16; it++) {
        int e = tid + it * 256;
        int i = e >> 6;
        int dk = e & 63;
        t[i][dk] = Vp[(size_t)(b * S + s0 + i) * D + h * 64 + dk];
    }
    __syncthreads();
#pragma unroll
    for (int it = 0; it < 16; it++) {
        int e = tid + it * 256;
        int dk = e >> 6;
        int j = e & 63;
        float v = t[j][dk];
        __nv_bfloat16 hi = __float2bfloat16_rn(v);
        __nv_bfloat16 lo = __float2bfloat16_rn(v - __bfloat162float(hi));
        size_t o = (size_t)(bh * 64 + dk) * S + s0 + j;
        g_Vthi[o] = hi;
        g_Vtlo[o] = lo;
    }
}

// ---------------------------------------------------------------------------
// Tensor-core causal flash attention (bf16x3), cp.async double-buffered.
// CTA = 128 q rows of one (b,h). 8 warps x 16 rows. K-tiles of 64.
// SMEM: 2 stages x 32KB. Stage layout: KHI@0 KLO@8192 VHI@16384 VLO@24576.
// Q staged into stage0 area before the pipeline starts.
// ---------------------------------------------------------------------------
#define FSA(row, bc) ((uint32_t)((row) * 128 + ((bc) ^ (((row) & 7) << 4))))
#define FLASH_SMEM 65536

__global__ __launch_bounds__(256) void flash_mma_kernel(float* __restrict__ Op) {
    extern __shared__ char sm[];
    uint32_t smb = smem_u32(sm);

    int tid = threadIdx.x;
    int w = tid >> 5;
    int lane = tid & 31;
    int qt = (int)gridDim.x - 1 - (int)blockIdx.x;   // heavy tiles first
    int bh = blockIdx.y;
    int b = bh >> 4;
    int h = bh & 15;
    int q0 = qt * 128;
    int r0 = lane >> 2;
    int qd = (lane & 3);
    int qrow = q0 + w * 16;

    size_t qkbase = (size_t)b * S * D + h * 64;
    size_t vtbase = (size_t)bh * 64 * S;

    // ---- stage Q (regular loads), build fragments ----
#pragma unroll
    for (int it = 0; it < 4; it++) {
        int ch = tid + it * 256;       // 0..1023
        int row = ch >> 3;
        int cc = ch & 7;
        uint32_t sa = FSA(row, cc * 16);
        *(uint4*)(sm + sa) = *((const uint4*)(g_Qhi + qkbase + (size_t)(q0 + row) * D) + cc);
        *(uint4*)(sm + 16384 + sa) = *((const uint4*)(g_Qlo + qkbase + (size_t)(q0 + row) * D) + cc);
    }
    __syncthreads();

    uint32_t qh[4][4], ql[4][4];
    {
        int rA = w * 16 + r0;
#pragma unroll
        for (int kk = 0; kk < 4; kk++) {
            int bc = kk * 32 + qd * 4;
            uint32_t s00 = FSA(rA, bc);
            uint32_t s10 = FSA(rA + 8, bc);
            uint32_t s01 = FSA(rA, bc + 16);
            uint32_t s11 = FSA(rA + 8, bc + 16);
            qh[kk][0] = *(const uint32_t*)(sm + s00);
            qh[kk][1] = *(const uint32_t*)(sm + s10);
            qh[kk][2] = *(const uint32_t*)(sm + s01);
            qh[kk][3] = *(const uint32_t*)(sm + s11);
            ql[kk][0] = *(const uint32_t*)(sm + 16384 + s00);
            ql[kk][1] = *(const uint32_t*)(sm + 16384 + s10);
            ql[kk][2] = *(const uint32_t*)(sm + 16384 + s01);
            ql[kk][3] = *(const uint32_t*)(sm + 16384 + s11);
        }
    }
    __syncthreads();   // all Q reads done before cp.async overwrites stage 0

    float o[8][4];
#pragma unroll
    for (int n = 0; n < 8; n++)
#pragma unroll
        for (int j = 0; j < 4; j++) o[n][j] = 0.0f;
    float m0 = -1e30f, m1 = -1e30f, l0 = 0.0f, l1 = 0.0f;

    int ktmax = 2 * qt + 1;

    // staging thread mapping (per tile: 512 x 16B)
    int srow0 = tid >> 3;          // rows 0..31 (it=0), +32 (it=1)
    int scc = (tid & 7);           // 16B chunk 0..7

    // prologue: prefetch tile 0 into stage 0
    {
        int k0 = 0;
#pragma unroll
        for (int it = 0; it < 2; it++) {
            int row = srow0 + it * 32;
            uint32_t sa = FSA(row, scc * 16);
            CP_ASYNC16(smb + sa,         (const uint4*)(g_Khi + qkbase + (size_t)(k0 + row) * D) + scc);
            CP_ASYNC16(smb + 8192 + sa,  (const uint4*)(g_Klo + qkbase + (size_t)(k0 + row) * D) + scc);
            CP_ASYNC16(smb + 16384 + sa, (const uint4*)(g_Vthi + vtbase + (size_t)row * S + k0) + scc);
            CP_ASYNC16(smb + 24576 + sa, (const uint4*)(g_Vtlo + vtbase + (size_t)row * S + k0) + scc);
        }
        CP_COMMIT();
    }

    for (int kt = 0; kt <= ktmax; kt++) {
        int k0 = kt * 64;
        char* buf = sm + (kt & 1) * 32768;

        if (kt < ktmax) {
            int kn = (kt + 1) * 64;
            uint32_t db = smb + ((kt + 1) & 1) * 32768;
#pragma unroll
            for (int it = 0; it < 2; it++) {
                int row = srow0 + it * 32;
                uint32_t sa = FSA(row, scc * 16);
                CP_ASYNC16(db + sa,         (const uint4*)(g_Khi + qkbase + (size_t)(kn + row) * D) + scc);
                CP_ASYNC16(db + 8192 + sa,  (const uint4*)(g_Klo + qkbase + (size_t)(kn + row) * D) + scc);
                CP_ASYNC16(db + 16384 + sa, (const uint4*)(g_Vthi + vtbase + (size_t)row * S + kn) + scc);
                CP_ASYNC16(db + 24576 + sa, (const uint4*)(g_Vtlo + vtbase + (size_t)row * S + kn) + scc);
            }
            CP_COMMIT();
            CP_WAIT(1);
        } else {
            CP_WAIT(0);
        }
        __syncthreads();

        if (k0 <= qrow + 15) {
            // ---- S = Q K^T ----
            float s[8][4];
#pragma unroll
            for (int n = 0; n < 8; n++)
#pragma unroll
                for (int j = 0; j < 4; j++) s[n][j] = 0.0f;
#pragma unroll
            for (int n = 0; n < 8; n++) {
                int br = n * 8 + r0;
#pragma unroll
                for (int kk = 0; kk < 4; kk++) {
                    int bc = kk * 32 + qd * 4;
                    uint32_t sa0 = FSA(br, bc);
                    uint32_t sa1 = FSA(br, bc + 16);
                    uint32_t bhf[2], blf[2];
                    bhf[0] = *(const uint32_t*)(buf + sa0);
                    bhf[1] = *(const uint32_t*)(buf + sa1);
                    blf[0] = *(const uint32_t*)(buf + 8192 + sa0);
                    blf[1] = *(const uint32_t*)(buf + 8192 + sa1);
                    mma16816(s[n], qh[kk], bhf);
                    mma16816(s[n], qh[kk], blf);
                    mma16816(s[n], ql[kk], bhf);
                }
            }

            // causal mask on diagonal-straddling tiles
            if (k0 + 63 > qrow) {
                int rq0 = qrow + r0;
#pragma unroll
                for (int n = 0; n < 8; n++) {
                    int c0 = k0 + n * 8 + qd * 2;
                    if (c0 > rq0) s[n][0] = -1e30f;
                    if (c0 + 1 > rq0) s[n][1] = -1e30f;
                    if (c0 > rq0 + 8) s[n][2] = -1e30f;
                    if (c0 + 1 > rq0 + 8) s[n][3] = -1e30f;
                }
            }

            // ---- online softmax ----
            float rm0 = -1e30f, rm1 = -1e30f;
#pragma unroll
            for (int n = 0; n < 8; n++) {
                rm0 = fmaxf(rm0, fmaxf(s[n][0], s[n][1]));
                rm1 = fmaxf(rm1, fmaxf(s[n][2], s[n][3]));
            }
            rm0 = fmaxf(rm0, __shfl_xor_sync(0xffffffffu, rm0, 1));
            rm0 = fmaxf(rm0, __shfl_xor_sync(0xffffffffu, rm0, 2));
            rm1 = fmaxf(rm1, __shfl_xor_sync(0xffffffffu, rm1, 1));
            rm1 = fmaxf(rm1, __shfl_xor_sync(0xffffffffu, rm1, 2));
            float mn0 = fmaxf(m0, rm0);
            float mn1 = fmaxf(m1, rm1);
            float al0 = exp2f((m0 - mn0) * LOG2E);
            float al1 = exp2f((m1 - mn1) * LOG2E);
            m0 = mn0; m1 = mn1;

            float rs0 = 0.0f, rs1 = 0.0f;
#pragma unroll
            for (int n = 0; n < 8; n++) {
                s[n][0] = exp2f((s[n][0] - mn0) * LOG2E);
                s[n][1] = exp2f((s[n][1] - mn0) * LOG2E);
                s[n][2] = exp2f((s[n][2] - mn1) * LOG2E);
                s[n][3] = exp2f((s[n][3] - mn1) * LOG2E);
                rs0 += s[n][0] + s[n][1];
                rs1 += s[n][2] + s[n][3];
            }
            rs0 += __shfl_xor_sync(0xffffffffu, rs0, 1);
            rs0 += __shfl_xor_sync(0xffffffffu, rs0, 2);
            rs1 += __shfl_xor_sync(0xffffffffu, rs1, 1);
            rs1 += __shfl_xor_sync(0xffffffffu, rs1, 2);
            l0 = l0 * al0 + rs0;
            l1 = l1 * al1 + rs1;
#pragma unroll
            for (int n = 0; n < 8; n++) {
                o[n][0] *= al0; o[n][1] *= al0;
                o[n][2] *= al1; o[n][3] *= al1;
            }

            // ---- P -> A fragments (hi/lo) ----
            uint32_t pah[4][4], pal[4][4];
#pragma unroll
            for (int kk = 0; kk < 4; kk++) {
                pack_hilo(s[2 * kk][0], s[2 * kk][1], pah[kk][0], pal[kk][0]);
                pack_hilo(s[2 * kk][2], s[2 * kk][3], pah[kk][1], pal[kk][1]);
                pack_hilo(s[2 * kk + 1][0], s[2 * kk + 1][1], pah[kk][2], pal[kk][2]);
                pack_hilo(s[2 * kk + 1][2], s[2 * kk + 1][3], pah[kk][3], pal[kk][3]);
            }

            // ---- O += P V ----
#pragma unroll
            for (int n = 0; n < 8; n++) {
                int vr = n * 8 + r0;
#pragma unroll
                for (int kk = 0; kk < 4; kk++) {
                    int bc = kk * 32 + qd * 4;
                    uint32_t sa0 = FSA(vr, bc);
                    uint32_t sa1 = FSA(vr, bc + 16);
                    uint32_t vhf[2], vlf[2];
                    vhf[0] = *(const uint32_t*)(buf + 16384 + sa0);
                    vhf[1] = *(const uint32_t*)(buf + 16384 + sa1);
                    vlf[0] = *(const uint32_t*)(buf + 24576 + sa0);
                    vlf[1] = *(const uint32_t*)(buf + 24576 + sa1);
                    mma16816(o[n], pah[kk], vhf);
                    mma16816(o[n], pah[kk], vlf);
                    mma16816(o[n], pal[kk], vhf);
                }
            }
        }
        __syncthreads();   // all warps done with buf before it is overwritten
    }

    // ---- epilogue ----
    float il0 = 1.0f / l0;
    float il1 = 1.0f / l1;
    int rg = q0 + w * 16 + r0;
#pragma unroll
    for (int n = 0; n < 8; n++) {
        int dk = n * 8 + qd * 2;
        *(float2*)(Op + qkbase + (size_t)rg * D + dk) = make_float2(o[n][0] * il0, o[n][1] * il0);
        *(float2*)(Op + qkbase + (size_t)(rg + 8) * D + dk) = make_float2(o[n][2] * il1, o[n][3] * il1);
    }
}

// ---------------------------------------------------------------------------
// Launch
// ---------------------------------------------------------------------------
extern "C" void kernel_launch(void* const* d_in, const int* in_sizes, int n_in,
                              void* d_out, int out_size)
{
    const float* q  = (const float*)d_in[0];
    const float* k  = (const float*)d_in[1];
    const float* v  = (const float*)d_in[2];
    const float* Wq = (const float*)d_in[3];
    const float* Wk = (const float*)d_in[4];
    const float* Wv = (const float*)d_in[5];
    const float* Wo = (const float*)d_in[6];
    const float* qw = (const float*)d_in[7];
    const float* kw = (const float*)d_in[8];
    float* out = (float*)d_out;

    float *Qp, *Kp, *Vp, *At;
    cudaGetSymbolAddress((void**)&Qp, g_Qp);
    cudaGetSymbolAddress((void**)&Kp, g_Kp);
    cudaGetSymbolAddress((void**)&Vp, g_Vp);
    cudaGetSymbolAddress((void**)&At, g_attn);

    // 1) RoPE tables
    rope_table_kernel<<<(S * 32 + 255) / 256, 256>>>();

    // 2) Q/K/V projections via bf16x3 mma.sync GEMM
    cudaFuncSetAttribute(gemm_mma_kernel, cudaFuncAttributeMaxDynamicSharedMemorySize, GEMM_SMEM);
    dim3 gproj(GN / 128, (B * S) / 128, 3);
    gemm_mma_kernel<<<gproj, 256, GEMM_SMEM>>>(q, k, v, Wq, Wk, Wv, Qp, Kp, Vp);

    // 3) per-head RMSNorm + RoPE -> bf16 hi/lo (Q scaled by 1/8)
    norm_rope_kernel<<<dim3((B * S * H) / 8, 2), 256>>>(Qp, Kp, qw, kw);

    // 3b) V -> transposed bf16 hi/lo
    v_transpose_kernel<<<dim3(S / 64, B * H), 256>>>(Vp);

    // 4) tensor-core causal flash attention (cp.async pipelined) -> g_attn
    cudaFuncSetAttribute(flash_mma_kernel, cudaFuncAttributeMaxDynamicSharedMemorySize, FLASH_SMEM);
    flash_mma_kernel<<<dim3(S / 128, B * H), 256, FLASH_SMEM>>>(At);

    // 5) output projection attn @ Wo^T -> d_out
    dim3 gout(GN / 128, (B * S) / 128, 1);
    gemm_mma_kernel<<<gout, 256, GEMM_SMEM>>>(At, At, At, Wo, Wo, Wo, out, out, out);
}